// round 1
// baseline (speedup 1.0000x reference)
#include <cuda_runtime.h>
#include <math.h>

#define BB 128
#define SS 512
#define DD 1024
#define GEN_V 50000
#define OUT_V 50257

// Scratch (allocation-free rule: __device__ globals)
__device__ float g_logits[BB * GEN_V];   // 25.6 MB
__device__ float g_interp[BB];
__device__ float g_rowmax[BB];
__device__ float g_rowsum[BB];

// ---------------------------------------------------------------------------
// Gate: interp[b] = sigmoid(x[b,:] . W_gate + b_gate)
// ---------------------------------------------------------------------------
__global__ void gate_kernel(const float* __restrict__ x,
                            const float* __restrict__ Wg,
                            const float* __restrict__ bg) {
    int b = blockIdx.x;
    int tid = threadIdx.x;
    float s = 0.f;
    for (int d = tid; d < DD; d += 256)
        s += x[b * DD + d] * Wg[d];
    __shared__ float red[256];
    red[tid] = s;
    __syncthreads();
    for (int off = 128; off > 0; off >>= 1) {
        if (tid < off) red[tid] += red[tid + off];
        __syncthreads();
    }
    if (tid == 0)
        g_interp[b] = 1.f / (1.f + expf(-(red[0] + bg[0])));
}

// ---------------------------------------------------------------------------
// GEMM: logits[b,v] = sum_d x[b,d] * W_gen[d,v] + b_gen[v]
// BM=128 (=B), BN=128, BK=8, 256 threads, 8x8 microtile
// ---------------------------------------------------------------------------
#define BM 128
#define BN 128
#define BK 8

__global__ __launch_bounds__(256, 2) void gemm_kernel(
    const float* __restrict__ A,    // [BB, DD]
    const float* __restrict__ W,    // [DD, GEN_V]
    const float* __restrict__ bias, // [GEN_V]
    float* __restrict__ C)          // [BB, GEN_V]
{
    __shared__ __align__(16) float As[BK][BM];
    __shared__ __align__(16) float Bs[BK][BN];

    const int bn = blockIdx.x * BN;
    const int tid = threadIdx.x;

    // A loader: 128 rows x 8 k -> each thread one float4 along k
    const int a_row  = tid >> 1;
    const int a_col4 = (tid & 1) * 4;
    // B loader: 8 k-rows x 128 v -> each thread one float4 along v
    const int b_row  = tid >> 5;
    const int b_col4 = (tid & 31) * 4;

    const int tx = tid & 15;
    const int ty = tid >> 4;
    const int cm0 = ty * 4;
    const int cm1 = ty * 4 + 64;
    const int cn0 = tx * 4;
    const int cn1 = tx * 4 + 64;

    float acc[8][8];
    #pragma unroll
    for (int i = 0; i < 8; i++)
        #pragma unroll
        for (int j = 0; j < 8; j++)
            acc[i][j] = 0.f;

    for (int k0 = 0; k0 < DD; k0 += BK) {
        // Load A tile (x is [128,1024] row-major; k contiguous)
        float4 av = *reinterpret_cast<const float4*>(&A[a_row * DD + k0 + a_col4]);
        As[a_col4 + 0][a_row] = av.x;
        As[a_col4 + 1][a_row] = av.y;
        As[a_col4 + 2][a_row] = av.z;
        As[a_col4 + 3][a_row] = av.w;

        // Load B tile (W is [1024, 50000] row-major; v contiguous, coalesced)
        int gv = bn + b_col4;
        float4 bv = make_float4(0.f, 0.f, 0.f, 0.f);
        if (gv < GEN_V)  // GEN_V % 4 == 0 -> a float4 is fully in or fully out
            bv = *reinterpret_cast<const float4*>(&W[(k0 + b_row) * (long)GEN_V + gv]);
        *reinterpret_cast<float4*>(&Bs[b_row][b_col4]) = bv;

        __syncthreads();

        #pragma unroll
        for (int k = 0; k < BK; k++) {
            float4 a0 = *reinterpret_cast<const float4*>(&As[k][cm0]);
            float4 a1 = *reinterpret_cast<const float4*>(&As[k][cm1]);
            float4 b0 = *reinterpret_cast<const float4*>(&Bs[k][cn0]);
            float4 b1 = *reinterpret_cast<const float4*>(&Bs[k][cn1]);
            float ar[8] = {a0.x, a0.y, a0.z, a0.w, a1.x, a1.y, a1.z, a1.w};
            float br[8] = {b0.x, b0.y, b0.z, b0.w, b1.x, b1.y, b1.z, b1.w};
            #pragma unroll
            for (int i = 0; i < 8; i++)
                #pragma unroll
                for (int j = 0; j < 8; j++)
                    acc[i][j] = fmaf(ar[i], br[j], acc[i][j]);
        }
        __syncthreads();
    }

    // Epilogue: add bias, guarded store
    #pragma unroll
    for (int i = 0; i < 8; i++) {
        int row = (i < 4) ? (cm0 + i) : (cm1 + i - 4);
        #pragma unroll
        for (int j = 0; j < 8; j++) {
            int col = bn + ((j < 4) ? (cn0 + j) : (cn1 + j - 4));
            if (col < GEN_V)
                C[row * (long)GEN_V + col] = acc[i][j] + bias[col];
        }
    }
}

// ---------------------------------------------------------------------------
// Row softmax statistics: max and sum(exp) per row
// ---------------------------------------------------------------------------
__global__ void rowstats_kernel() {
    int b = blockIdx.x;
    int tid = threadIdx.x;
    const float* row = g_logits + (long)b * GEN_V;

    __shared__ float red[256];

    float m = -INFINITY;
    for (int v = tid; v < GEN_V; v += 256)
        m = fmaxf(m, row[v]);
    red[tid] = m;
    __syncthreads();
    for (int off = 128; off > 0; off >>= 1) {
        if (tid < off) red[tid] = fmaxf(red[tid], red[tid + off]);
        __syncthreads();
    }
    float rmax = red[0];
    __syncthreads();

    float s = 0.f;
    for (int v = tid; v < GEN_V; v += 256)
        s += expf(row[v] - rmax);
    red[tid] = s;
    __syncthreads();
    for (int off = 128; off > 0; off >>= 1) {
        if (tid < off) red[tid] += red[tid + off];
        __syncthreads();
    }
    if (tid == 0) {
        g_rowmax[b] = rmax;
        g_rowsum[b] = red[0];
    }
}

// ---------------------------------------------------------------------------
// Zero the output (poisoned to 0xAA by the harness)
// ---------------------------------------------------------------------------
__global__ void zero_kernel(float* __restrict__ out, long n) {
    long i = (long)blockIdx.x * blockDim.x + threadIdx.x;
    long stride = (long)gridDim.x * blockDim.x;
    for (; i < n; i += stride) out[i] = 0.f;
}

// ---------------------------------------------------------------------------
// Scatter generation probs: out[b, g2o[v]] += interp[b] * softmax(logits)[b,v]
// ---------------------------------------------------------------------------
__global__ void scatter_gen_kernel(const int* __restrict__ g2o,
                                   float* __restrict__ out) {
    int b = blockIdx.y;
    int v = blockIdx.x * 256 + threadIdx.x;
    if (v >= GEN_V) return;
    float scale = g_interp[b] / g_rowsum[b];
    float p = expf(g_logits[(long)b * GEN_V + v] - g_rowmax[b]) * scale;
    atomicAdd(&out[(long)b * OUT_V + g2o[v]], p);
}

// ---------------------------------------------------------------------------
// Scatter pointer probs: out[b, i2o[ctx[b,s]]] += (1-interp[b]) * alphas[b,s]
// ---------------------------------------------------------------------------
__global__ void scatter_ptr_kernel(const float* __restrict__ alphas,
                                   const int* __restrict__ ctx,
                                   const int* __restrict__ i2o,
                                   float* __restrict__ out) {
    int b = blockIdx.y;
    int s = blockIdx.x * 256 + threadIdx.x;
    if (s >= SS) return;
    float w = (1.f - g_interp[b]) * alphas[b * SS + s];
    int o = i2o[ctx[b * SS + s]];
    atomicAdd(&out[(long)b * OUT_V + o], w);
}

// ---------------------------------------------------------------------------
// Launch
// Inputs (metadata order): x, alphas, W_gate, b_gate, W_gen, b_gen,
//                          ctx_inp, gen_to_out, inp_to_out
// ---------------------------------------------------------------------------
extern "C" void kernel_launch(void* const* d_in, const int* in_sizes, int n_in,
                              void* d_out, int out_size) {
    const float* x      = (const float*)d_in[0];
    const float* alphas = (const float*)d_in[1];
    const float* W_gate = (const float*)d_in[2];
    const float* b_gate = (const float*)d_in[3];
    const float* W_gen  = (const float*)d_in[4];
    const float* b_gen  = (const float*)d_in[5];
    const int* ctx_inp  = (const int*)d_in[6];
    const int* g2o      = (const int*)d_in[7];
    const int* i2o      = (const int*)d_in[8];
    float* out = (float*)d_out;

    float* logits;
    cudaGetSymbolAddress((void**)&logits, g_logits);

    // 1. Gate
    gate_kernel<<<BB, 256>>>(x, W_gate, b_gate);

    // 2. GEMM -> logits
    dim3 ggrid((GEN_V + BN - 1) / BN, 1);
    gemm_kernel<<<ggrid, 256>>>(x, W_gen, b_gen, logits);

    // 3. Row softmax stats
    rowstats_kernel<<<BB, 256>>>();

    // 4. Zero output
    zero_kernel<<<1024, 256>>>(out, (long)BB * OUT_V);

    // 5. Scatter gen probs
    dim3 sgrid((GEN_V + 255) / 256, BB);
    scatter_gen_kernel<<<sgrid, 256>>>(g2o, out);

    // 6. Scatter pointer probs
    dim3 pgrid((SS + 255) / 256, BB);
    scatter_ptr_kernel<<<pgrid, 256>>>(alphas, ctx_inp, i2o, out);
}

// round 3
// speedup vs baseline: 2.3028x; 2.3028x over previous
#include <cuda_runtime.h>
#include <cuda_bf16.h>
#include <stdint.h>
#include <math.h>

#define BB 128
#define SS 512
#define DD 1024
#define GEN_V 50000
#define OUT_V 50257

#define NT 256                        // N columns per CTA
#define KC 32                         // K per chunk
#define NCHUNK (DD / KC)              // 32
#define NCTA ((GEN_V + NT - 1) / NT)  // 196

// ---------------------------------------------------------------------------
// Device scratch (allocation-free rule: __device__ globals)
// ---------------------------------------------------------------------------
__device__ float   g_probs[(size_t)BB * GEN_V];   // exp(logits), 25.6 MB
__device__ float   g_interp[BB];
__device__ float   g_rowsum[BB];
// Pre-swizzled bf16 A, per K-chunk: chunk layout = 128m x 32k, 8KB each
__device__ uint8_t g_Ahi[NCHUNK * 8192];
__device__ uint8_t g_Alo[NCHUNK * 8192];

// ---------------------------------------------------------------------------
// Helpers (family-safe PTX only: sm_80-level mma/ldmatrix/cp.async)
// ---------------------------------------------------------------------------
__device__ __forceinline__ uint32_t smem_u32(const void* p) {
    uint32_t a;
    asm("{ .reg .u64 t; cvta.to.shared.u64 t, %1; cvt.u32.u64 %0, t; }" : "=r"(a) : "l"(p));
    return a;
}

#define LDSM4(r, addr)                                                          \
    asm volatile("ldmatrix.sync.aligned.m8n8.x4.shared.b16 {%0,%1,%2,%3}, [%4];" \
        : "=r"((r)[0]), "=r"((r)[1]), "=r"((r)[2]), "=r"((r)[3]) : "r"(addr))

#define LDSM4T(r, addr)                                                               \
    asm volatile("ldmatrix.sync.aligned.m8n8.x4.trans.shared.b16 {%0,%1,%2,%3}, [%4];" \
        : "=r"((r)[0]), "=r"((r)[1]), "=r"((r)[2]), "=r"((r)[3]) : "r"(addr))

#define MMA_BF16(ac, a, b0, b1)                                                  \
    asm volatile("mma.sync.aligned.m16n8k16.row.col.f32.bf16.bf16.f32 "          \
        "{%0,%1,%2,%3}, {%4,%5,%6,%7}, {%8,%9}, {%0,%1,%2,%3};"                  \
        : "+f"((ac)[0]), "+f"((ac)[1]), "+f"((ac)[2]), "+f"((ac)[3])             \
        : "r"((a)[0]), "r"((a)[1]), "r"((a)[2]), "r"((a)[3]), "r"(b0), "r"(b1))

#define CPASYNC16(dst, src) \
    asm volatile("cp.async.ca.shared.global [%0], [%1], 16;" :: "r"(dst), "l"(src))
#define CPASYNC_COMMIT() asm volatile("cp.async.commit_group;")
#define CPASYNC_WAIT0()  asm volatile("cp.async.wait_group 0;" ::: "memory")

// A chunk swizzle: plain offset o = m*64 + k*2, swizzled o ^ (((m>>1)&7)*16)
__device__ __host__ __forceinline__ uint32_t a_swz(int m, int k) {
    uint32_t o = (uint32_t)(m * 64 + k * 2);
    return o ^ ((((uint32_t)m >> 1) & 7u) << 4);
}

// ---------------------------------------------------------------------------
// SMEM layout (dynamic): bias 1KB | buf0 48KB | buf1 48KB
// per-buf: AH 0 | AL 8K | BH 16K | BL 32K
// ---------------------------------------------------------------------------
#define SM_BIAS  0
#define SM_BUF   1024
#define BUFSZ    49152
#define OFF_AH   0
#define OFF_AL   8192
#define OFF_BH   16384
#define OFF_BL   32768
#define SMEM_DYN (SM_BUF + 2 * BUFSZ)

// ---------------------------------------------------------------------------
// Gate (also zeroes g_rowsum)
// ---------------------------------------------------------------------------
__global__ void gate_kernel(const float* __restrict__ x,
                            const float* __restrict__ Wg,
                            const float* __restrict__ bg) {
    int b = blockIdx.x;
    int tid = threadIdx.x;
    if (tid == 0) g_rowsum[b] = 0.f;
    float s = 0.f;
    for (int d = tid; d < DD; d += 256)
        s += x[b * DD + d] * Wg[d];
    __shared__ float red[256];
    red[tid] = s;
    __syncthreads();
    for (int off = 128; off > 0; off >>= 1) {
        if (tid < off) red[tid] += red[tid + off];
        __syncthreads();
    }
    if (tid == 0)
        g_interp[b] = 1.f / (1.f + expf(-(red[0] + bg[0])));
}

// ---------------------------------------------------------------------------
// Pre-convert x -> bf16 hi/lo into swizzled per-chunk layout
// ---------------------------------------------------------------------------
__global__ void prepA_kernel(const float* __restrict__ x) {
    int m = blockIdx.x;
    for (int k = threadIdx.x; k < DD; k += 256) {
        float v = x[m * DD + k];
        __nv_bfloat16 h = __float2bfloat16(v);
        __nv_bfloat16 l = __float2bfloat16(v - __bfloat162float(h));
        int c = k >> 5, kk = k & 31;
        uint32_t off = (uint32_t)c * 8192u + a_swz(m, kk);
        *(__nv_bfloat16*)(g_Ahi + off) = h;
        *(__nv_bfloat16*)(g_Alo + off) = l;
    }
}

// ---------------------------------------------------------------------------
// GEMM via mma.sync bf16 (3-term hi/lo split) + fused exp/rowsum epilogue
// 512 threads, warp grid 4(m) x 4(n), warp tile 32x64
// ---------------------------------------------------------------------------
__global__ __launch_bounds__(512, 1) void gemm_mma_kernel(
    const float* __restrict__ W, const float* __restrict__ bias)
{
    extern __shared__ __align__(16) uint8_t smem[];
    const int tid = threadIdx.x;
    const int wid = tid >> 5;
    const int lid = tid & 31;
    const int wm = wid >> 2;          // 0..3 (M direction)
    const int wn = wid & 3;           // 0..3 (N direction)
    const int n0 = blockIdx.x * NT;

    const uint32_t sb = smem_u32(smem);

    // bias tile
    if (tid < NT) {
        int gn = n0 + tid;
        ((float*)(smem + SM_BIAS))[tid] = (gn < GEN_V) ? bias[gn] : 0.f;
    }

    // B prefetch assignment: two (k,g) pairs per thread
    const int bk0 = tid >> 5;          // 0..15
    const int bk1 = bk0 + 16;          // 16..31
    const int bg8 = (tid & 31) * 8;    // n offset within tile (0..248)
    const bool bok = (n0 + bg8) < GEN_V;

    float4 pf[4];  // [k0 lo4, k0 hi4, k1 lo4, k1 hi4]

    auto loadB = [&](int c) {
        const float* p0 = W + (size_t)(c * KC + bk0) * GEN_V + n0 + bg8;
        const float* p1 = W + (size_t)(c * KC + bk1) * GEN_V + n0 + bg8;
        if (bok) {
            pf[0] = *(const float4*)(p0);
            pf[1] = *(const float4*)(p0 + 4);
            pf[2] = *(const float4*)(p1);
            pf[3] = *(const float4*)(p1 + 4);
        } else {
            pf[0] = pf[1] = pf[2] = pf[3] = make_float4(0.f, 0.f, 0.f, 0.f);
        }
    };

    auto storeB = [&](uint32_t bufbase) {
        #pragma unroll
        for (int half = 0; half < 2; half++) {
            int k = half ? bk1 : bk0;
            float v[8] = {pf[half*2].x, pf[half*2].y, pf[half*2].z, pf[half*2].w,
                          pf[half*2+1].x, pf[half*2+1].y, pf[half*2+1].z, pf[half*2+1].w};
            uint32_t hpack[4], lpack[4];
            #pragma unroll
            for (int i = 0; i < 4; i++) {
                __nv_bfloat16 h0 = __float2bfloat16(v[2*i]);
                __nv_bfloat16 h1 = __float2bfloat16(v[2*i+1]);
                float l0 = v[2*i]   - __bfloat162float(h0);
                float l1 = v[2*i+1] - __bfloat162float(h1);
                __nv_bfloat162 hp; hp.x = h0; hp.y = h1;
                __nv_bfloat162 lp; lp.x = __float2bfloat16(l0); lp.y = __float2bfloat16(l1);
                hpack[i] = *(uint32_t*)&hp;
                lpack[i] = *(uint32_t*)&lp;
            }
            uint32_t off = (uint32_t)k * 512u + (((uint32_t)bg8 * 2u) ^ (((uint32_t)k & 7u) << 4));
            *(uint4*)(smem + (bufbase - sb) + OFF_BH + off) = *(uint4*)hpack;
            *(uint4*)(smem + (bufbase - sb) + OFF_BL + off) = *(uint4*)lpack;
        }
    };

    auto loadA_async = [&](int c, uint32_t bufbase) {
        const uint8_t* srcH = g_Ahi + (size_t)c * 8192 + tid * 16;
        const uint8_t* srcL = g_Alo + (size_t)c * 8192 + tid * 16;
        CPASYNC16(bufbase + OFF_AH + tid * 16, srcH);
        CPASYNC16(bufbase + OFF_AL + tid * 16, srcL);
    };

    float acc[2][8][4];
    #pragma unroll
    for (int i = 0; i < 2; i++)
        #pragma unroll
        for (int j = 0; j < 8; j++)
            #pragma unroll
            for (int q = 0; q < 4; q++)
                acc[i][j][q] = 0.f;

    const uint32_t buf0 = sb + SM_BUF;
    const uint32_t buf1 = sb + SM_BUF + BUFSZ;

    // Precompute ldmatrix lane addresses (offsets within buffer)
    // A: tiles i (m16), halves by ks at runtime
    const int arow = wm * 32 + (lid & 15);                 // + i*16
    const int akb  = ((lid >> 4) << 3) * 2;                // + ks*32 bytes
    // B: nb = wn*64 + j*16
    const int bkrow_base = (lid & 15);                     // + ks*16
    const int bnoff = ((lid >> 4) << 3);                   // 0 or 8

    // Prologue
    loadB(0);
    loadA_async(0, buf0);
    CPASYNC_COMMIT();
    storeB(buf0);
    loadB(1);
    CPASYNC_WAIT0();
    __syncthreads();

    for (int c = 0; c < NCHUNK; c++) {
        const uint32_t bufbase = (c & 1) ? buf1 : buf0;

        // ---- MMA over this chunk ----
        #pragma unroll
        for (int ks = 0; ks < 2; ks++) {
            uint32_t ahi[2][4], alo[2][4];
            #pragma unroll
            for (int i = 0; i < 2; i++) {
                int row = arow + i * 16;
                uint32_t o = (uint32_t)(row * 64 + ks * 32 + akb);
                uint32_t swz = o ^ ((((uint32_t)row >> 1) & 7u) << 4);
                LDSM4(ahi[i], bufbase + OFF_AH + swz);
                LDSM4(alo[i], bufbase + OFF_AL + swz);
            }
            #pragma unroll
            for (int j = 0; j < 4; j++) {
                int krow = ks * 16 + bkrow_base;
                int n = wn * 64 + j * 16 + bnoff;
                uint32_t off = (uint32_t)krow * 512u +
                               (((uint32_t)n * 2u) ^ (((uint32_t)krow & 7u) << 4));
                uint32_t bh[4], bl[4];
                LDSM4T(bh, bufbase + OFF_BH + off);
                LDSM4T(bl, bufbase + OFF_BL + off);
                #pragma unroll
                for (int i = 0; i < 2; i++) {
                    #pragma unroll
                    for (int h = 0; h < 2; h++) {
                        float* ac = acc[i][j * 2 + h];
                        MMA_BF16(ac, ahi[i], bh[2*h], bh[2*h+1]);
                        MMA_BF16(ac, ahi[i], bl[2*h], bl[2*h+1]);
                        MMA_BF16(ac, alo[i], bh[2*h], bh[2*h+1]);
                    }
                }
            }
        }

        // ---- Stage next chunk ----
        if (c < NCHUNK - 1) {
            __syncthreads();
            const uint32_t nxt = (c & 1) ? buf0 : buf1;
            loadA_async(c + 1, nxt);
            CPASYNC_COMMIT();
            storeB(nxt);
            if (c + 2 < NCHUNK) loadB(c + 2);
            CPASYNC_WAIT0();
            __syncthreads();
        }
    }

    // ---- Epilogue: bias + exp + store + rowsum ----
    const float* biasS = (const float*)(smem + SM_BIAS);
    #pragma unroll
    for (int i = 0; i < 2; i++) {
        int r0 = wm * 32 + i * 16 + (lid >> 2);
        int r1 = r0 + 8;
        float s0 = 0.f, s1 = 0.f;
        #pragma unroll
        for (int j = 0; j < 8; j++) {
            int cidx = wn * 64 + j * 8 + (lid & 3) * 2;
            int gn = n0 + cidx;
            bool ok = gn < GEN_V;
            float b0 = biasS[cidx], b1 = biasS[cidx + 1];
            float p00 = __expf(acc[i][j][0] + b0);
            float p01 = __expf(acc[i][j][1] + b1);
            float p10 = __expf(acc[i][j][2] + b0);
            float p11 = __expf(acc[i][j][3] + b1);
            if (ok) {
                *(float2*)(g_probs + (size_t)r0 * GEN_V + gn) = make_float2(p00, p01);
                *(float2*)(g_probs + (size_t)r1 * GEN_V + gn) = make_float2(p10, p11);
                s0 += p00 + p01;
                s1 += p10 + p11;
            }
        }
        s0 += __shfl_xor_sync(0xFFFFFFFF, s0, 1);
        s0 += __shfl_xor_sync(0xFFFFFFFF, s0, 2);
        s1 += __shfl_xor_sync(0xFFFFFFFF, s1, 1);
        s1 += __shfl_xor_sync(0xFFFFFFFF, s1, 2);
        if ((lid & 3) == 0) {
            atomicAdd(&g_rowsum[r0], s0);
            atomicAdd(&g_rowsum[r1], s1);
        }
    }
}

// ---------------------------------------------------------------------------
// Zero output
// ---------------------------------------------------------------------------
__global__ void zero4_kernel(float4* __restrict__ out, int n4) {
    int i = blockIdx.x * 256 + threadIdx.x;
    int stride = gridDim.x * 256;
    for (; i < n4; i += stride) out[i] = make_float4(0.f, 0.f, 0.f, 0.f);
}

// ---------------------------------------------------------------------------
// Scatter gen probs: out[b, g2o[v]] += (interp[b]/rowsum[b]) * probs[b,v]
// ---------------------------------------------------------------------------
__global__ void scatter_gen_kernel(const int* __restrict__ g2o,
                                   float* __restrict__ out) {
    int b = blockIdx.y;
    int i = blockIdx.x * 256 + threadIdx.x;
    if (i >= GEN_V / 4) return;
    float sc = g_interp[b] / g_rowsum[b];
    float4 p = ((const float4*)(g_probs + (size_t)b * GEN_V))[i];
    int4 m = ((const int4*)g2o)[i];
    float* ob = out + (size_t)b * OUT_V;
    atomicAdd(ob + m.x, p.x * sc);
    atomicAdd(ob + m.y, p.y * sc);
    atomicAdd(ob + m.z, p.z * sc);
    atomicAdd(ob + m.w, p.w * sc);
}

// ---------------------------------------------------------------------------
// Scatter pointer probs
// ---------------------------------------------------------------------------
__global__ void scatter_ptr_kernel(const float* __restrict__ alphas,
                                   const int* __restrict__ ctx,
                                   const int* __restrict__ i2o,
                                   float* __restrict__ out) {
    int b = blockIdx.y;
    int s = blockIdx.x * 256 + threadIdx.x;
    if (s >= SS) return;
    float w = (1.f - g_interp[b]) * alphas[b * SS + s];
    int o = i2o[ctx[b * SS + s]];
    atomicAdd(&out[(size_t)b * OUT_V + o], w);
}

// ---------------------------------------------------------------------------
// Launch. Inputs: x, alphas, W_gate, b_gate, W_gen, b_gen, ctx_inp,
//                 gen_to_out, inp_to_out
// ---------------------------------------------------------------------------
extern "C" void kernel_launch(void* const* d_in, const int* in_sizes, int n_in,
                              void* d_out, int out_size) {
    const float* x      = (const float*)d_in[0];
    const float* alphas = (const float*)d_in[1];
    const float* W_gate = (const float*)d_in[2];
    const float* b_gate = (const float*)d_in[3];
    const float* W_gen  = (const float*)d_in[4];
    const float* b_gen  = (const float*)d_in[5];
    const int* ctx_inp  = (const int*)d_in[6];
    const int* g2o      = (const int*)d_in[7];
    const int* i2o      = (const int*)d_in[8];
    float* out = (float*)d_out;

    cudaFuncSetAttribute(gemm_mma_kernel,
                         cudaFuncAttributeMaxDynamicSharedMemorySize, SMEM_DYN);

    gate_kernel<<<BB, 256>>>(x, W_gate, b_gate);
    prepA_kernel<<<BB, 256>>>(x);
    gemm_mma_kernel<<<NCTA, 512, SMEM_DYN>>>(W_gen, b_gen);
    zero4_kernel<<<2048, 256>>>((float4*)out, (BB * OUT_V) / 4);
    dim3 sgrid((GEN_V / 4 + 255) / 256, BB);
    scatter_gen_kernel<<<sgrid, 256>>>(g2o, out);
    dim3 pgrid((SS + 255) / 256, BB);
    scatter_ptr_kernel<<<pgrid, 256>>>(alphas, ctx_inp, i2o, out);
}

// round 4
// speedup vs baseline: 3.2675x; 1.4189x over previous
#include <cuda_runtime.h>
#include <cuda_bf16.h>
#include <stdint.h>
#include <math.h>

#define BB 128
#define SS 512
#define DD 1024
#define GEN_V 50000
#define OUT_V 50257

#define NT 128                        // N columns per CTA
#define KC 32                         // K per chunk
#define NCHUNK (DD / KC)              // 32
#define NCTA ((GEN_V + NT - 1) / NT)  // 391

// ---------------------------------------------------------------------------
// Device scratch
// ---------------------------------------------------------------------------
__device__ float   g_interp[BB];
__device__ float   g_rowsum[BB];
__device__ uint8_t g_Ahi[NCHUNK * 8192];   // pre-swizzled bf16 A, 8KB per K-chunk

// ---------------------------------------------------------------------------
// Helpers (family-safe PTX only)
// ---------------------------------------------------------------------------
__device__ __forceinline__ uint32_t smem_u32(const void* p) {
    uint32_t a;
    asm("{ .reg .u64 t; cvta.to.shared.u64 t, %1; cvt.u32.u64 %0, t; }" : "=r"(a) : "l"(p));
    return a;
}

#define LDSM4(r, addr)                                                          \
    asm volatile("ldmatrix.sync.aligned.m8n8.x4.shared.b16 {%0,%1,%2,%3}, [%4];" \
        : "=r"((r)[0]), "=r"((r)[1]), "=r"((r)[2]), "=r"((r)[3]) : "r"(addr))

#define LDSM4T(r, addr)                                                               \
    asm volatile("ldmatrix.sync.aligned.m8n8.x4.trans.shared.b16 {%0,%1,%2,%3}, [%4];" \
        : "=r"((r)[0]), "=r"((r)[1]), "=r"((r)[2]), "=r"((r)[3]) : "r"(addr))

#define MMA_BF16(ac, a, b0, b1)                                                  \
    asm volatile("mma.sync.aligned.m16n8k16.row.col.f32.bf16.bf16.f32 "          \
        "{%0,%1,%2,%3}, {%4,%5,%6,%7}, {%8,%9}, {%0,%1,%2,%3};"                  \
        : "+f"((ac)[0]), "+f"((ac)[1]), "+f"((ac)[2]), "+f"((ac)[3])             \
        : "r"((a)[0]), "r"((a)[1]), "r"((a)[2]), "r"((a)[3]), "r"(b0), "r"(b1))

#define CPASYNC16(dst, src) \
    asm volatile("cp.async.ca.shared.global [%0], [%1], 16;" :: "r"(dst), "l"(src))
#define CPASYNC_COMMIT() asm volatile("cp.async.commit_group;")
#define CPASYNC_WAIT0()  asm volatile("cp.async.wait_group 0;" ::: "memory")

// pack two fp32 -> bf16x2 (lo -> low half, hi -> high half), round-to-nearest
__device__ __forceinline__ uint32_t pack_bf16(float lo, float hi) {
    uint32_t r;
    asm("cvt.rn.bf16x2.f32 %0, %1, %2;" : "=r"(r) : "f"(hi), "f"(lo));
    return r;
}

// A chunk swizzle: o = m*64 + k*2, swizzled o ^ (((m>>1)&7)*16)
__device__ __host__ __forceinline__ uint32_t a_swz(int m, int k) {
    uint32_t o = (uint32_t)(m * 64 + k * 2);
    return o ^ ((((uint32_t)m >> 1) & 7u) << 4);
}

// ---------------------------------------------------------------------------
// Gate (also zeroes g_rowsum)
// ---------------------------------------------------------------------------
__global__ void gate_kernel(const float* __restrict__ x,
                            const float* __restrict__ Wg,
                            const float* __restrict__ bg) {
    int b = blockIdx.x;
    int tid = threadIdx.x;
    if (tid == 0) g_rowsum[b] = 0.f;
    float s = 0.f;
    for (int d = tid; d < DD; d += 256)
        s += x[b * DD + d] * Wg[d];
    __shared__ float red[256];
    red[tid] = s;
    __syncthreads();
    for (int off = 128; off > 0; off >>= 1) {
        if (tid < off) red[tid] += red[tid + off];
        __syncthreads();
    }
    if (tid == 0)
        g_interp[b] = 1.f / (1.f + expf(-(red[0] + bg[0])));
}

// ---------------------------------------------------------------------------
// Pre-convert x -> bf16 into swizzled per-chunk layout
// ---------------------------------------------------------------------------
__global__ void prepA_kernel(const float* __restrict__ x) {
    int m = blockIdx.x;
    for (int k = threadIdx.x; k < DD; k += 256) {
        float v = x[m * DD + k];
        int c = k >> 5, kk = k & 31;
        *(__nv_bfloat16*)(g_Ahi + (uint32_t)c * 8192u + a_swz(m, kk)) =
            __float2bfloat16(v);
    }
}

// ---------------------------------------------------------------------------
// Zero output
// ---------------------------------------------------------------------------
__global__ void zero4_kernel(float4* __restrict__ out, int n4) {
    int i = blockIdx.x * 256 + threadIdx.x;
    int stride = gridDim.x * 256;
    for (; i < n4; i += stride) out[i] = make_float4(0.f, 0.f, 0.f, 0.f);
}

// ---------------------------------------------------------------------------
// Pure-bf16 GEMM (mma.sync) + fused exp + direct atomic scatter epilogue.
// 256 threads, warp grid 4(m) x 2(n), warp tile 32x64, tile 128 x NT(128).
// ---------------------------------------------------------------------------
__global__ __launch_bounds__(256, 2) void gemm_mma_kernel(
    const float* __restrict__ W, const float* __restrict__ bias,
    const int* __restrict__ g2o, float* __restrict__ out)
{
    __shared__ float sBias[NT];
    __shared__ int   sG2O[NT];
    __shared__ __align__(16) uint8_t sBuf[2][16384];   // per buf: AH 8K | BH 8K
    #define OFF_BH 8192

    const int tid = threadIdx.x;
    const int wid = tid >> 5;
    const int lid = tid & 31;
    const int wm = wid >> 1;          // 0..3 (M)
    const int wn = wid & 1;           // 0..1 (N)
    const int n0 = blockIdx.x * NT;

    // bias + index map tiles
    if (tid < NT) {
        int gn = n0 + tid;
        bool ok = gn < GEN_V;
        sBias[tid] = ok ? bias[gn] : 0.f;
        sG2O[tid]  = ok ? g2o[gn] : 0;
    }

    // B loader assignment: 2 k-rows x 8 n per thread
    const int bk0 = tid >> 4;           // 0..15
    const int bk1 = bk0 + 16;           // 16..31
    const int ng  = (tid & 15) * 8;     // n offset (0..120)
    const bool bok = (n0 + ng) < GEN_V;

    float4 pf[4];   // k0: pf[0..1], k1: pf[2..3]

    auto loadB = [&](int c) {
        const float* p0 = W + (size_t)(c * KC + bk0) * GEN_V + n0 + ng;
        const float* p1 = W + (size_t)(c * KC + bk1) * GEN_V + n0 + ng;
        if (bok) {
            pf[0] = *(const float4*)(p0);
            pf[1] = *(const float4*)(p0 + 4);
            pf[2] = *(const float4*)(p1);
            pf[3] = *(const float4*)(p1 + 4);
        } else {
            pf[0] = pf[1] = pf[2] = pf[3] = make_float4(0.f, 0.f, 0.f, 0.f);
        }
    };

    auto storeB = [&](int buf) {
        #pragma unroll
        for (int half = 0; half < 2; half++) {
            int k = half ? bk1 : bk0;
            float4 a = pf[half * 2], b4 = pf[half * 2 + 1];
            uint32_t u[4];
            u[0] = pack_bf16(a.x, a.y);
            u[1] = pack_bf16(a.z, a.w);
            u[2] = pack_bf16(b4.x, b4.y);
            u[3] = pack_bf16(b4.z, b4.w);
            uint32_t off = (uint32_t)k * 256u +
                           (((uint32_t)ng * 2u) ^ (((uint32_t)k & 7u) << 4));
            *(uint4*)(sBuf[buf] + OFF_BH + off) = *(uint4*)u;
        }
    };

    const uint32_t sb0 = smem_u32(sBuf[0]);
    const uint32_t sb1 = smem_u32(sBuf[1]);

    auto loadA_async = [&](int c, int buf) {
        const uint8_t* src = g_Ahi + (size_t)c * 8192 + tid * 32;
        uint32_t dst = (buf ? sb1 : sb0) + tid * 32;
        CPASYNC16(dst, src);
        CPASYNC16(dst + 16, src + 16);
    };

    float acc[2][8][4];
    #pragma unroll
    for (int i = 0; i < 2; i++)
        #pragma unroll
        for (int j = 0; j < 8; j++)
            #pragma unroll
            for (int q = 0; q < 4; q++)
                acc[i][j][q] = 0.f;

    // ldmatrix lane address components
    const int arow = wm * 32 + (lid & 15);          // + i*16
    const int akb  = (lid >> 4) << 4;               // 0 or 16 bytes
    const int bkrow_base = (lid & 15);              // + ks*16
    const int bnoff = (lid >> 4) << 3;              // 0 or 8

    // Prologue
    loadB(0);
    loadA_async(0, 0);
    CPASYNC_COMMIT();
    storeB(0);
    loadB(1);
    CPASYNC_WAIT0();
    __syncthreads();

    #pragma unroll 1
    for (int c = 0; c < NCHUNK; c++) {
        const int buf = c & 1;
        const uint32_t bufbase = buf ? sb1 : sb0;

        // ---- MMA over this chunk ----
        #pragma unroll
        for (int ks = 0; ks < 2; ks++) {
            uint32_t ah[2][4];
            #pragma unroll
            for (int i = 0; i < 2; i++) {
                int row = arow + i * 16;
                uint32_t o = (uint32_t)(row * 64 + ks * 32 + akb);
                uint32_t swz = o ^ ((((uint32_t)row >> 1) & 7u) << 4);
                LDSM4(ah[i], bufbase + swz);
            }
            #pragma unroll
            for (int j = 0; j < 4; j++) {
                int krow = ks * 16 + bkrow_base;
                int n = wn * 64 + j * 16 + bnoff;
                uint32_t off = (uint32_t)krow * 256u +
                               (((uint32_t)n * 2u) ^ (((uint32_t)krow & 7u) << 4));
                uint32_t bh[4];
                LDSM4T(bh, bufbase + OFF_BH + off);
                #pragma unroll
                for (int i = 0; i < 2; i++) {
                    MMA_BF16(acc[i][j * 2 + 0], ah[i], bh[0], bh[1]);
                    MMA_BF16(acc[i][j * 2 + 1], ah[i], bh[2], bh[3]);
                }
            }
        }

        // ---- Stage next chunk ----
        if (c < NCHUNK - 1) {
            __syncthreads();
            loadA_async(c + 1, buf ^ 1);
            CPASYNC_COMMIT();
            storeB(buf ^ 1);
            if (c + 2 < NCHUNK) loadB(c + 2);
            CPASYNC_WAIT0();
            __syncthreads();
        }
    }

    // ---- Epilogue: bias + exp + direct atomic scatter + rowsum ----
    #pragma unroll
    for (int i = 0; i < 2; i++) {
        int r0 = wm * 32 + i * 16 + (lid >> 2);
        int r1 = r0 + 8;
        float s0 = 0.f, s1 = 0.f;
        #pragma unroll
        for (int j = 0; j < 8; j++) {
            int cidx = wn * 64 + j * 8 + (lid & 3) * 2;
            int gn = n0 + cidx;
            if (gn < GEN_V) {
                float b0 = sBias[cidx], b1 = sBias[cidx + 1];
                int o0 = sG2O[cidx], o1 = sG2O[cidx + 1];
                float p00 = __expf(acc[i][j][0] + b0);
                float p01 = __expf(acc[i][j][1] + b1);
                float p10 = __expf(acc[i][j][2] + b0);
                float p11 = __expf(acc[i][j][3] + b1);
                atomicAdd(out + (size_t)r0 * OUT_V + o0, p00);
                atomicAdd(out + (size_t)r0 * OUT_V + o1, p01);
                atomicAdd(out + (size_t)r1 * OUT_V + o0, p10);
                atomicAdd(out + (size_t)r1 * OUT_V + o1, p11);
                s0 += p00 + p01;
                s1 += p10 + p11;
            }
        }
        s0 += __shfl_xor_sync(0xFFFFFFFF, s0, 1);
        s0 += __shfl_xor_sync(0xFFFFFFFF, s0, 2);
        s1 += __shfl_xor_sync(0xFFFFFFFF, s1, 1);
        s1 += __shfl_xor_sync(0xFFFFFFFF, s1, 2);
        if ((lid & 3) == 0) {
            atomicAdd(&g_rowsum[r0], s0);
            atomicAdd(&g_rowsum[r1], s1);
        }
    }
}

// ---------------------------------------------------------------------------
// Rescale: out[b,:] *= interp[b] / rowsum[b]
// ---------------------------------------------------------------------------
__global__ void rescale_kernel(float* __restrict__ out) {
    int b = blockIdx.y;
    float s = g_interp[b] / g_rowsum[b];
    float* ob = out + (size_t)b * OUT_V;
    for (int j = blockIdx.x * 256 + threadIdx.x; j < OUT_V; j += gridDim.x * 256)
        ob[j] *= s;
}

// ---------------------------------------------------------------------------
// Scatter pointer probs (after rescale)
// ---------------------------------------------------------------------------
__global__ void scatter_ptr_kernel(const float* __restrict__ alphas,
                                   const int* __restrict__ ctx,
                                   const int* __restrict__ i2o,
                                   float* __restrict__ out) {
    int b = blockIdx.y;
    int s = blockIdx.x * 256 + threadIdx.x;
    if (s >= SS) return;
    float w = (1.f - g_interp[b]) * alphas[b * SS + s];
    int o = i2o[ctx[b * SS + s]];
    atomicAdd(&out[(size_t)b * OUT_V + o], w);
}

// ---------------------------------------------------------------------------
// Launch. Inputs: x, alphas, W_gate, b_gate, W_gen, b_gen, ctx_inp,
//                 gen_to_out, inp_to_out
// ---------------------------------------------------------------------------
extern "C" void kernel_launch(void* const* d_in, const int* in_sizes, int n_in,
                              void* d_out, int out_size) {
    const float* x      = (const float*)d_in[0];
    const float* alphas = (const float*)d_in[1];
    const float* W_gate = (const float*)d_in[2];
    const float* b_gate = (const float*)d_in[3];
    const float* W_gen  = (const float*)d_in[4];
    const float* b_gen  = (const float*)d_in[5];
    const int* ctx_inp  = (const int*)d_in[6];
    const int* g2o      = (const int*)d_in[7];
    const int* i2o      = (const int*)d_in[8];
    float* out = (float*)d_out;

    gate_kernel<<<BB, 256>>>(x, W_gate, b_gate);
    prepA_kernel<<<BB, 256>>>(x);
    zero4_kernel<<<2048, 256>>>((float4*)out, (BB * OUT_V) / 4);
    gemm_mma_kernel<<<NCTA, 256>>>(W_gen, b_gen, g2o, out);
    dim3 rgrid(64, BB);
    rescale_kernel<<<rgrid, 256>>>(out);
    dim3 pgrid((SS + 255) / 256, BB);
    scatter_ptr_kernel<<<pgrid, 256>>>(alphas, ctx_inp, i2o, out);
}